// round 14
// baseline (speedup 1.0000x reference)
#include <cuda_runtime.h>
#include <cuda_fp16.h>
#include <cstdint>

// Problem dims
#define Bz 4096
#define Iz 256
#define Oz 256
#define Kz 8192   // 2 * Iz * 16 ; k = s*4096 + i*16 + g

// Scratch globals (no allocs allowed)
// g_A: pre-swizzled tile image: block (kc, mg) = 16KB = 128 rows x 128B (SW
//      pattern identical to the GEMM smem stage). kc = s*64 + i/4, mg = b/128.
__device__ __half g_A[(size_t)Bz * Kz];        // features fp16 (64 MB)
__device__ __half g_W[(size_t)Oz * Kz];        // weights  fp16 (4 MB), row-major [o][k]
__device__ float  g_part[2][(size_t)Bz * Oz];  // split-K partials (8 MB)

// ---------------------------------------------------------------- helpers --
__device__ __forceinline__ uint32_t smem_u32(const void* p) {
    uint32_t a;
    asm("{ .reg .u64 t; cvta.to.shared.u64 t, %1; cvt.u32.u64 %0, t; }"
        : "=r"(a) : "l"(p));
    return a;
}
__device__ __forceinline__ void cp16(uint32_t dst, const void* src) {
    asm volatile("cp.async.cg.shared.global [%0], [%1], 16;" :: "r"(dst), "l"(src) : "memory");
}
__device__ __forceinline__ void cp_commit() {
    asm volatile("cp.async.commit_group;" ::: "memory");
}
__device__ __forceinline__ void cp_wait2() {
    asm volatile("cp.async.wait_group 2;" ::: "memory");
}
__device__ __forceinline__ void ldsm4(uint32_t* r, uint32_t a) {
    asm volatile("ldmatrix.sync.aligned.m8n8.x4.shared.b16 {%0,%1,%2,%3}, [%4];"
                 : "=r"(r[0]), "=r"(r[1]), "=r"(r[2]), "=r"(r[3]) : "r"(a));
}
__device__ __forceinline__ void mma16816(float* d, const uint32_t* a, const uint32_t* b) {
    asm volatile(
        "mma.sync.aligned.m16n8k16.row.col.f32.f16.f16.f32 "
        "{%0,%1,%2,%3}, {%4,%5,%6,%7}, {%8,%9}, {%0,%1,%2,%3};"
        : "+f"(d[0]), "+f"(d[1]), "+f"(d[2]), "+f"(d[3])
        : "r"(a[0]), "r"(a[1]), "r"(a[2]), "r"(a[3]), "r"(b[0]), "r"(b[1]));
}
__device__ __forceinline__ uint32_t packh(__half a, __half b) {
    return ((uint32_t)__half_as_ushort(b) << 16) | __half_as_ushort(a);
}

// swizzled within-tile byte offset for (row, 16B-chunk ck), 128B rows
#define SWADDR(row, ck) ((uint32_t)((row) * 128 + (((ck) ^ ((row) & 7)) << 4)))

// ------------------------------------------------------- merged pre-pass --
// blocks [0,2048): features -> g_A as pre-swizzled tile images.
//   block = (mg = blk&31, iq = blk>>5): 128 rows x {kc = iq, kc = 64+iq}.
// blocks [2048,4096): W fp16 convert (row-major [o][k]).
__global__ __launch_bounds__(256) void prep_kernel(const float* __restrict__ x,
                                                   const float* __restrict__ C) {
    if (blockIdx.x < 2048) {
        __shared__ unsigned char sm[32768];   // two 16KB tile images (s=0, s=1)
        int mg = blockIdx.x & 31;
        int iq = blockIdx.x >> 5;
        int t  = threadIdx.x;
        int r  = t & 127;                     // tile row
        int b  = mg * 128 + r;
        int ilh = t >> 7;                     // 0/1: which i-pair

#pragma unroll
        for (int u = 0; u < 2; u++) {
            int i_local = ilh * 2 + u;        // 0..3
            int i = iq * 4 + i_local;
            float xv = x[b * 256 + i];
            float en = __expf(-0.02f * xv);   // MUFU.EX2 (+FMUL)
            float ep = __expf( 0.02f * xv);

#pragma unroll
            for (int s = 0; s < 2; s++) {
                float e1 = s ? ep : en;
                float e2 = e1 * e1;
                float st = e2 * e1;           // e^{±0.06x}
                float f  = e2 * st;           // e^{±0.10x}
                float s2 = st * st;
                float a = f, bb = f * st;     // even / odd g chains
                uint32_t h[8];
#pragma unroll
                for (int q = 0; q < 8; q++) {
                    __half2 hp = __floats2half2_rn(a, bb);
                    h[q] = *reinterpret_cast<uint32_t*>(&hp);
                    a *= s2; bb *= s2;
                }
                int j0 = i_local * 2;
                unsigned char* half_base = sm + s * 16384;
                *reinterpret_cast<uint4*>(half_base + SWADDR(r, j0)) =
                    make_uint4(h[0], h[1], h[2], h[3]);
                *reinterpret_cast<uint4*>(half_base + SWADDR(r, j0 + 1)) =
                    make_uint4(h[4], h[5], h[6], h[7]);
            }
        }
        __syncthreads();

        // coalesced copy-out: thread t moves 128B linearly
        int s   = t >> 7;                     // which 16KB half
        int off = (t & 127) * 128;
        int kc  = s * 64 + iq;
        const uint4* src = reinterpret_cast<const uint4*>(sm + s * 16384 + off);
        uint4* dst = reinterpret_cast<uint4*>(
            reinterpret_cast<unsigned char*>(g_A) +
            ((size_t)kc * 32 + mg) * 16384 + off);
#pragma unroll
        for (int q = 0; q < 8; q++) dst[q] = src[q];
    } else {
        int t = (blockIdx.x - 2048) * 256 + threadIdx.x;
        size_t lin = (size_t)t * 4;
        int s  = (int)(lin >> 20);
        int o  = (int)((lin >> 12) & 255);
        int kp = (int)(lin & 4095);
        float4 v = *reinterpret_cast<const float4*>(C + lin);
        uint32_t h0 = packh(__float2half_rn(v.x), __float2half_rn(v.y));
        uint32_t h1 = packh(__float2half_rn(v.z), __float2half_rn(v.w));
        size_t op = (size_t)o * Kz + (size_t)s * 4096 + kp;
        *reinterpret_cast<uint2*>(g_W + op) = make_uint2(h0, h1);
    }
}

// ------------------------------------------------- split-K mma.sync GEMM --
// g_part[z][B][O] = A[:, z*4096:(z+1)*4096] * W^T  (fp32 accum)
// CTA tile 128x128, K-chunk 64, 4-stage ring, 8 warps of 32x64.
// grid (2, 32, 2) = 128 CTAs, 1/SM, one wave. A loads are LINEAR copies.
#define BM 128
#define BN 128
#define NSTG 4
#define STG_BYTES 32768        // A 16K | W 16K
#define NCHUNK 64              // per split: 4096 / 64
#define SMEM_SIZE (NSTG * STG_BYTES + 1024)

__device__ __forceinline__ void load_stage(uint32_t orig, int st, int c,
                                           int t, int mg, int n0, int z) {
    uint32_t sb = orig + st * STG_BYTES;
    // A: gmem image == smem image; pure linear copy
    const unsigned char* abase = reinterpret_cast<const unsigned char*>(g_A) +
        ((size_t)(z * 64 + c) * 32 + mg) * 16384;
#pragma unroll
    for (int j = 0; j < 4; j++) {
        int idx = t + j * 256;
        cp16(sb + idx * 16, abase + idx * 16);
    }
    // W: row-major with swizzled smem placement (unchanged)
    size_t ko = (size_t)z * 4096 + (size_t)c * 64;
#pragma unroll
    for (int j = 0; j < 4; j++) {
        int idx = t + j * 256;
        int row = idx >> 3, ck = idx & 7;
        cp16(sb + 16384 + SWADDR(row, ck), g_W + (size_t)(n0 + row) * Kz + ko + ck * 8);
    }
}

__global__ __launch_bounds__(256, 1) void gemm_kernel() {
    extern __shared__ unsigned char smem_raw[];
    uint32_t orig = (smem_u32(smem_raw) + 1023u) & ~1023u;

    int t    = threadIdx.x;
    int lane = t & 31;
    int wid  = t >> 5;
    int wm   = wid >> 1;         // 0..3 -> 32-row band
    int wn   = wid & 1;          // 0..1 -> 64-col band
    int mg   = blockIdx.y;
    int m0   = mg * BM;
    int n0   = blockIdx.x * BN;
    int z    = blockIdx.z;

    float acc[2][8][4];
#pragma unroll
    for (int mt = 0; mt < 2; mt++)
#pragma unroll
        for (int nt = 0; nt < 8; nt++)
#pragma unroll
            for (int r = 0; r < 4; r++) acc[mt][nt][r] = 0.0f;

    // per-lane ldmatrix address components
    int a_row_base = wm * 32 + (lane & 15);                 // + mt*16
    int a_ckx      = lane >> 4;                             // k-half select
    int b_n_off    = ((lane >> 4) & 1) * 8 + (lane & 7);    // + wn*64 + q*16
    int b_ckx      = (lane >> 3) & 1;

    // prologue: 3 stages in flight
    load_stage(orig, 0, 0, t, mg, n0, z); cp_commit();
    load_stage(orig, 1, 1, t, mg, n0, z); cp_commit();
    load_stage(orig, 2, 2, t, mg, n0, z); cp_commit();

    for (int c = 0; c < NCHUNK; c++) {
        cp_wait2();
        __syncthreads();   // single barrier per chunk (orders stage reuse too)

        if (c + 3 < NCHUNK) load_stage(orig, (c + 3) & 3, c + 3, t, mg, n0, z);
        cp_commit();

        uint32_t sb = orig + (c & 3) * STG_BYTES;
#pragma unroll
        for (int ks = 0; ks < 4; ks++) {
            uint32_t av[2][4], bv[4][4];
#pragma unroll
            for (int mt = 0; mt < 2; mt++)
                ldsm4(av[mt], sb + SWADDR(a_row_base + mt * 16, ks * 2 + a_ckx));
#pragma unroll
            for (int q = 0; q < 4; q++) {
                int n = wn * 64 + q * 16 + b_n_off;
                ldsm4(bv[q], sb + 16384 + SWADDR(n, ks * 2 + b_ckx));
            }
#pragma unroll
            for (int mt = 0; mt < 2; mt++)
#pragma unroll
                for (int nt = 0; nt < 8; nt++) {
                    int q = nt >> 1, pr = (nt & 1) * 2;
                    mma16816(acc[mt][nt], av[mt], &bv[q][pr]);
                }
        }
    }

    // epilogue: store partials (fragment layout of m16n8 f32 d-regs)
    float* pout = g_part[z];
#pragma unroll
    for (int mt = 0; mt < 2; mt++) {
        int row = m0 + wm * 32 + mt * 16 + (lane >> 2);
#pragma unroll
        for (int nt = 0; nt < 8; nt++) {
            int col = n0 + wn * 64 + nt * 8 + (lane & 3) * 2;
            float2 r0, r1;
            r0.x = acc[mt][nt][0];
            r0.y = acc[mt][nt][1];
            r1.x = acc[mt][nt][2];
            r1.y = acc[mt][nt][3];
            *reinterpret_cast<float2*>(pout + (size_t)row * Oz + col) = r0;
            *reinterpret_cast<float2*>(pout + (size_t)(row + 8) * Oz + col) = r1;
        }
    }
}

// ------------------------------------------------------------ reduce ------
// out = part0 + part1 + bias
__global__ __launch_bounds__(256) void reduce_kernel(const float* __restrict__ bias,
                                                     float* __restrict__ out) {
    size_t lin = ((size_t)blockIdx.x * 256 + threadIdx.x) * 4;
    int col = (int)(lin & 255);
    float4 p0 = *reinterpret_cast<const float4*>(&g_part[0][lin]);
    float4 p1 = *reinterpret_cast<const float4*>(&g_part[1][lin]);
    float4 bv = *reinterpret_cast<const float4*>(bias + col);
    float4 r;
    r.x = p0.x + p1.x + bv.x;
    r.y = p0.y + p1.y + bv.y;
    r.z = p0.z + p1.z + bv.z;
    r.w = p0.w + p1.w + bv.w;
    *reinterpret_cast<float4*>(out + lin) = r;
}

// -------------------------------------------------------------- launcher --
extern "C" void kernel_launch(void* const* d_in, const int* in_sizes, int n_in,
                              void* d_out, int out_size) {
    const float* x    = (const float*)d_in[0];
    const float* coef = (const float*)d_in[1];
    const float* bias = (const float*)d_in[2];
    float* out = (float*)d_out;

    static int configured = 0;
    if (!configured) {
        cudaFuncSetAttribute(gemm_kernel,
                             cudaFuncAttributeMaxDynamicSharedMemorySize, SMEM_SIZE);
        configured = 1;
    }

    prep_kernel<<<4096, 256>>>(x, coef);
    dim3 grid(Oz / BN, Bz / BM, 2);   // (2, 32, 2) = 128 CTAs
    gemm_kernel<<<grid, 256, SMEM_SIZE>>>();
    reduce_kernel<<<(Bz * Oz) / 1024, 256>>>(bias, out);
}

// round 15
// speedup vs baseline: 1.3053x; 1.3053x over previous
#include <cuda_runtime.h>
#include <cuda_fp16.h>
#include <cstdint>

// Problem dims
#define Bz 4096
#define Iz 256
#define Oz 256
#define Kz 8192   // 2 * Iz * 16 ; k = s*4096 + i*16 + g

// Scratch globals (no allocs allowed)
__device__ __half g_A[(size_t)Bz * Kz];   // features fp16 (64 MB)
__device__ __half g_W[(size_t)Oz * Kz];   // weights  fp16 (4 MB), row-major [o][k]

// ---------------------------------------------------------------- helpers --
__device__ __forceinline__ uint32_t smem_u32(const void* p) {
    uint32_t a;
    asm("{ .reg .u64 t; cvta.to.shared.u64 t, %1; cvt.u32.u64 %0, t; }"
        : "=r"(a) : "l"(p));
    return a;
}
__device__ __forceinline__ void cp16(uint32_t dst, const void* src) {
    asm volatile("cp.async.cg.shared.global [%0], [%1], 16;" :: "r"(dst), "l"(src) : "memory");
}
__device__ __forceinline__ void cp_commit() {
    asm volatile("cp.async.commit_group;" ::: "memory");
}
__device__ __forceinline__ void cp_wait2() {
    asm volatile("cp.async.wait_group 2;" ::: "memory");
}
__device__ __forceinline__ void ldsm4(uint32_t* r, uint32_t a) {
    asm volatile("ldmatrix.sync.aligned.m8n8.x4.shared.b16 {%0,%1,%2,%3}, [%4];"
                 : "=r"(r[0]), "=r"(r[1]), "=r"(r[2]), "=r"(r[3]) : "r"(a));
}
__device__ __forceinline__ void mma16816(float* d, const uint32_t* a, const uint32_t* b) {
    asm volatile(
        "mma.sync.aligned.m16n8k16.row.col.f32.f16.f16.f32 "
        "{%0,%1,%2,%3}, {%4,%5,%6,%7}, {%8,%9}, {%0,%1,%2,%3};"
        : "+f"(d[0]), "+f"(d[1]), "+f"(d[2]), "+f"(d[3])
        : "r"(a[0]), "r"(a[1]), "r"(a[2]), "r"(a[3]), "r"(b[0]), "r"(b[1]));
}
__device__ __forceinline__ void redadd(float* p, float v) {
    asm volatile("red.global.add.f32 [%0], %1;" :: "l"(p), "f"(v) : "memory");
}
__device__ __forceinline__ uint32_t packh(__half a, __half b) {
    return ((uint32_t)__half_as_ushort(b) << 16) | __half_as_ushort(a);
}

// swizzled within-tile byte offset for (row, 16B-chunk ck), 128B rows
#define SWADDR(row, ck) ((uint32_t)((row) * 128 + (((ck) ^ ((row) & 7)) << 4)))

// ------------------------------------------------------- merged pre-pass --
// blocks [0,4096): features (2 MUFU) -> g_A   (R13-proven layout/pattern)
// blocks [4096,6144): W fp16 convert
// blocks [6144,7168): out = bias (init for GEMM's red.add epilogue)
__global__ __launch_bounds__(256) void prep_kernel(const float* __restrict__ x,
                                                   const float* __restrict__ C,
                                                   const float* __restrict__ bias,
                                                   float* __restrict__ out) {
    if (blockIdx.x < 4096) {
        int idx = blockIdx.x * 256 + threadIdx.x;    // b*256 + i
        float xv = x[idx];

        float e  = __expf(0.02f * xv);
        float r  = __fdividef(1.0f, e);
        float e2 = e * e,  e3 = e2 * e,  e5 = e2 * e3;
        float r2 = r * r,  r3 = r2 * r,  r5 = r2 * r3;
        float tn = r3, tp = e3;      // steps  e^{∓0.06x}
        float fn = r5, fp = e5;      // starts e^{∓0.10x}

        uint32_t nw[8], pw[8];
#pragma unroll
        for (int q = 0; q < 8; q++) {
            __half n0 = __float2half_rn(fn); fn *= tn;
            __half n1 = __float2half_rn(fn); fn *= tn;
            nw[q] = packh(n0, n1);
            __half p0 = __float2half_rn(fp); fp *= tp;
            __half p1 = __float2half_rn(fp); fp *= tp;
            pw[q] = packh(p0, p1);
        }

        size_t base = ((size_t)(idx >> 8)) * Kz + (size_t)(idx & 255) * 16;
        uint4* dn = reinterpret_cast<uint4*>(g_A + base);          // s=0
        uint4* dp = reinterpret_cast<uint4*>(g_A + base + 4096);   // s=1
        dn[0] = make_uint4(nw[0], nw[1], nw[2], nw[3]);
        dn[1] = make_uint4(nw[4], nw[5], nw[6], nw[7]);
        dp[0] = make_uint4(pw[0], pw[1], pw[2], pw[3]);
        dp[1] = make_uint4(pw[4], pw[5], pw[6], pw[7]);
    } else if (blockIdx.x < 6144) {
        int t = (blockIdx.x - 4096) * 256 + threadIdx.x;
        size_t lin = (size_t)t * 4;
        int s  = (int)(lin >> 20);
        int o  = (int)((lin >> 12) & 255);
        int kp = (int)(lin & 4095);
        float4 v = *reinterpret_cast<const float4*>(C + lin);
        uint32_t h0 = packh(__float2half_rn(v.x), __float2half_rn(v.y));
        uint32_t h1 = packh(__float2half_rn(v.z), __float2half_rn(v.w));
        size_t op = (size_t)o * Kz + (size_t)s * 4096 + kp;
        *reinterpret_cast<uint2*>(g_W + op) = make_uint2(h0, h1);
    } else {
        size_t lin = ((size_t)(blockIdx.x - 6144) * 256 + threadIdx.x) * 4;
        int col = (int)(lin & 255);
        *reinterpret_cast<float4*>(out + lin) =
            *reinterpret_cast<const float4*>(bias + col);
    }
}

// ------------------------------------------------- split-K mma.sync GEMM --
// out += A[:, z*4096:(z+1)*4096] * W^T  via red.global.add (out = bias first)
// CTA tile 128x128, K-chunk 64, 4-stage ring, 8 warps of 32x64.
// grid (2, 32, 2) = 128 CTAs, 1/SM, one wave. Fragments double-buffered.
#define BM 128
#define BN 128
#define NSTG 4
#define STG_BYTES 32768        // A 16K | W 16K
#define NCHUNK 64              // per split: 4096 / 64
#define SMEM_SIZE (NSTG * STG_BYTES + 1024)

__device__ __forceinline__ void load_stage(uint32_t orig, int st, int c,
                                           int t, int m0, int n0, size_t kbase) {
    uint32_t sb = orig + st * STG_BYTES;
    size_t ko = kbase + (size_t)c * 64;
#pragma unroll
    for (int j = 0; j < 4; j++) {          // A: 128 rows x 8 chunks = 1024
        int idx = t + j * 256;
        int row = idx >> 3, ck = idx & 7;
        cp16(sb + SWADDR(row, ck), g_A + (size_t)(m0 + row) * Kz + ko + ck * 8);
    }
#pragma unroll
    for (int j = 0; j < 4; j++) {          // W: 128 rows x 8 chunks = 1024
        int idx = t + j * 256;
        int row = idx >> 3, ck = idx & 7;
        cp16(sb + 16384 + SWADDR(row, ck), g_W + (size_t)(n0 + row) * Kz + ko + ck * 8);
    }
}

__global__ __launch_bounds__(256, 1) void gemm_kernel(float* __restrict__ out) {
    extern __shared__ unsigned char smem_raw[];
    uint32_t orig = (smem_u32(smem_raw) + 1023u) & ~1023u;

    int t    = threadIdx.x;
    int lane = t & 31;
    int wid  = t >> 5;
    int wm   = wid >> 1;         // 0..3 -> 32-row band
    int wn   = wid & 1;          // 0..1 -> 64-col band
    int m0   = blockIdx.y * BM;
    int n0   = blockIdx.x * BN;
    int z    = blockIdx.z;
    size_t kbase = (size_t)z * 4096;

    float acc[2][8][4];
#pragma unroll
    for (int mt = 0; mt < 2; mt++)
#pragma unroll
        for (int nt = 0; nt < 8; nt++)
#pragma unroll
            for (int r = 0; r < 4; r++) acc[mt][nt][r] = 0.0f;

    // per-lane ldmatrix address components
    int a_row_base = wm * 32 + (lane & 15);                 // + mt*16
    int a_ckx      = lane >> 4;                             // k-half select
    int b_n_off    = ((lane >> 4) & 1) * 8 + (lane & 7);    // + wn*64 + q*16
    int b_ckx      = (lane >> 3) & 1;

    // prologue: 3 stages in flight
    load_stage(orig, 0, 0, t, m0, n0, kbase); cp_commit();
    load_stage(orig, 1, 1, t, m0, n0, kbase); cp_commit();
    load_stage(orig, 2, 2, t, m0, n0, kbase); cp_commit();

    for (int c = 0; c < NCHUNK; c++) {
        cp_wait2();
        __syncthreads();   // single barrier per chunk (orders stage reuse too)

        if (c + 3 < NCHUNK) load_stage(orig, (c + 3) & 3, c + 3, t, m0, n0, kbase);
        cp_commit();

        uint32_t sb = orig + (c & 3) * STG_BYTES;

        // fragment double-buffer: load ks+1 while computing ks
        uint32_t av[2][2][4], bv[2][4][4];
#pragma unroll
        for (int mt = 0; mt < 2; mt++)
            ldsm4(av[0][mt], sb + SWADDR(a_row_base + mt * 16, a_ckx));
#pragma unroll
        for (int q = 0; q < 4; q++)
            ldsm4(bv[0][q], sb + 16384 + SWADDR(wn * 64 + q * 16 + b_n_off, b_ckx));

#pragma unroll
        for (int ks = 0; ks < 4; ks++) {
            int cur = ks & 1, nxt = cur ^ 1;
            if (ks < 3) {
#pragma unroll
                for (int mt = 0; mt < 2; mt++)
                    ldsm4(av[nxt][mt],
                          sb + SWADDR(a_row_base + mt * 16, (ks + 1) * 2 + a_ckx));
#pragma unroll
                for (int q = 0; q < 4; q++)
                    ldsm4(bv[nxt][q],
                          sb + 16384 + SWADDR(wn * 64 + q * 16 + b_n_off,
                                              (ks + 1) * 2 + b_ckx));
            }
#pragma unroll
            for (int mt = 0; mt < 2; mt++)
#pragma unroll
                for (int nt = 0; nt < 8; nt++) {
                    int q = nt >> 1, pr = (nt & 1) * 2;
                    mma16816(acc[mt][nt], av[cur][mt], &bv[cur][q][pr]);
                }
        }
    }

    // epilogue: red.global.add into out (pre-initialized with bias)
#pragma unroll
    for (int mt = 0; mt < 2; mt++) {
        int row = m0 + wm * 32 + mt * 16 + (lane >> 2);
#pragma unroll
        for (int nt = 0; nt < 8; nt++) {
            int col = n0 + wn * 64 + nt * 8 + (lane & 3) * 2;
            float* p0 = out + (size_t)row * Oz + col;
            float* p1 = out + (size_t)(row + 8) * Oz + col;
            redadd(p0,     acc[mt][nt][0]);
            redadd(p0 + 1, acc[mt][nt][1]);
            redadd(p1,     acc[mt][nt][2]);
            redadd(p1 + 1, acc[mt][nt][3]);
        }
    }
}

// -------------------------------------------------------------- launcher --
extern "C" void kernel_launch(void* const* d_in, const int* in_sizes, int n_in,
                              void* d_out, int out_size) {
    const float* x    = (const float*)d_in[0];
    const float* coef = (const float*)d_in[1];
    const float* bias = (const float*)d_in[2];
    float* out = (float*)d_out;

    static int configured = 0;
    if (!configured) {
        cudaFuncSetAttribute(gemm_kernel,
                             cudaFuncAttributeMaxDynamicSharedMemorySize, SMEM_SIZE);
        configured = 1;
    }

    prep_kernel<<<7168, 256>>>(x, coef, bias, out);
    dim3 grid(Oz / BN, Bz / BM, 2);   // (2, 32, 2) = 128 CTAs
    gemm_kernel<<<grid, 256, SMEM_SIZE>>>(out);
}

// round 16
// speedup vs baseline: 1.3808x; 1.0578x over previous
#include <cuda_runtime.h>
#include <cuda_fp16.h>
#include <cstdint>

// Problem dims
#define Bz 4096
#define Iz 256
#define Oz 256
#define Kz 8192   // 2 * Iz * 16 ; k = s*4096 + i*16 + g

// Scratch globals (no allocs allowed)
__device__ __half g_A[(size_t)Bz * Kz];   // features fp16 (64 MB)
__device__ __half g_W[(size_t)Oz * Kz];   // weights  fp16 (4 MB), row-major [o][k]

// ---------------------------------------------------------------- helpers --
__device__ __forceinline__ uint32_t smem_u32(const void* p) {
    uint32_t a;
    asm("{ .reg .u64 t; cvta.to.shared.u64 t, %1; cvt.u32.u64 %0, t; }"
        : "=r"(a) : "l"(p));
    return a;
}
__device__ __forceinline__ void cp16(uint32_t dst, const void* src) {
    asm volatile("cp.async.cg.shared.global [%0], [%1], 16;" :: "r"(dst), "l"(src) : "memory");
}
__device__ __forceinline__ void cp_commit() {
    asm volatile("cp.async.commit_group;" ::: "memory");
}
__device__ __forceinline__ void cp_wait1() {
    asm volatile("cp.async.wait_group 1;" ::: "memory");
}
__device__ __forceinline__ void ldsm4(uint32_t* r, uint32_t a) {
    asm volatile("ldmatrix.sync.aligned.m8n8.x4.shared.b16 {%0,%1,%2,%3}, [%4];"
                 : "=r"(r[0]), "=r"(r[1]), "=r"(r[2]), "=r"(r[3]) : "r"(a));
}
__device__ __forceinline__ void mma16816(float* d, const uint32_t* a, const uint32_t* b) {
    asm volatile(
        "mma.sync.aligned.m16n8k16.row.col.f32.f16.f16.f32 "
        "{%0,%1,%2,%3}, {%4,%5,%6,%7}, {%8,%9}, {%0,%1,%2,%3};"
        : "+f"(d[0]), "+f"(d[1]), "+f"(d[2]), "+f"(d[3])
        : "r"(a[0]), "r"(a[1]), "r"(a[2]), "r"(a[3]), "r"(b[0]), "r"(b[1]));
}
__device__ __forceinline__ void redadd(float* p, float v) {
    asm volatile("red.global.add.f32 [%0], %1;" :: "l"(p), "f"(v) : "memory");
}
__device__ __forceinline__ uint32_t packh(__half a, __half b) {
    return ((uint32_t)__half_as_ushort(b) << 16) | __half_as_ushort(a);
}

// swizzled within-tile byte offset for (row, 16B-chunk ck), 128B rows
#define SWADDR(row, ck) ((uint32_t)((row) * 128 + (((ck) ^ ((row) & 7)) << 4)))

// ------------------------------------------------------- merged pre-pass --
// blocks [0,4096): features (2 MUFU) -> g_A
// blocks [4096,6144): W fp16 convert
// blocks [6144,7168): out = bias (init for GEMM's red.add epilogue)
__global__ __launch_bounds__(256) void prep_kernel(const float* __restrict__ x,
                                                   const float* __restrict__ C,
                                                   const float* __restrict__ bias,
                                                   float* __restrict__ out) {
    if (blockIdx.x < 4096) {
        int idx = blockIdx.x * 256 + threadIdx.x;    // b*256 + i
        float xv = x[idx];

        float e  = __expf(0.02f * xv);
        float r  = __fdividef(1.0f, e);
        float e2 = e * e,  e3 = e2 * e,  e5 = e2 * e3;
        float r2 = r * r,  r3 = r2 * r,  r5 = r2 * r3;
        float tn = r3, tp = e3;      // steps  e^{∓0.06x}
        float fn = r5, fp = e5;      // starts e^{∓0.10x}

        uint32_t nw[8], pw[8];
#pragma unroll
        for (int q = 0; q < 8; q++) {
            __half n0 = __float2half_rn(fn); fn *= tn;
            __half n1 = __float2half_rn(fn); fn *= tn;
            nw[q] = packh(n0, n1);
            __half p0 = __float2half_rn(fp); fp *= tp;
            __half p1 = __float2half_rn(fp); fp *= tp;
            pw[q] = packh(p0, p1);
        }

        size_t base = ((size_t)(idx >> 8)) * Kz + (size_t)(idx & 255) * 16;
        uint4* dn = reinterpret_cast<uint4*>(g_A + base);          // s=0
        uint4* dp = reinterpret_cast<uint4*>(g_A + base + 4096);   // s=1
        dn[0] = make_uint4(nw[0], nw[1], nw[2], nw[3]);
        dn[1] = make_uint4(nw[4], nw[5], nw[6], nw[7]);
        dp[0] = make_uint4(pw[0], pw[1], pw[2], pw[3]);
        dp[1] = make_uint4(pw[4], pw[5], pw[6], pw[7]);
    } else if (blockIdx.x < 6144) {
        int t = (blockIdx.x - 4096) * 256 + threadIdx.x;
        size_t lin = (size_t)t * 4;
        int s  = (int)(lin >> 20);
        int o  = (int)((lin >> 12) & 255);
        int kp = (int)(lin & 4095);
        float4 v = *reinterpret_cast<const float4*>(C + lin);
        uint32_t h0 = packh(__float2half_rn(v.x), __float2half_rn(v.y));
        uint32_t h1 = packh(__float2half_rn(v.z), __float2half_rn(v.w));
        size_t op = (size_t)o * Kz + (size_t)s * 4096 + kp;
        *reinterpret_cast<uint2*>(g_W + op) = make_uint2(h0, h1);
    } else {
        size_t lin = ((size_t)(blockIdx.x - 6144) * 256 + threadIdx.x) * 4;
        int col = (int)(lin & 255);
        *reinterpret_cast<float4*>(out + lin) =
            *reinterpret_cast<const float4*>(bias + col);
    }
}

// ------------------------------------------------- split-K mma.sync GEMM --
// out += A[:, z*2048:(z+1)*2048] * W^T  via red.global.add (out = bias first)
// CTA tile 128x128, K-chunk 64, 3-stage ring, 8 warps of 32x64.
// grid (2, 32, 4) = 256 CTAs, 2 CTAs/SM resident.
#define BM 128
#define BN 128
#define NSTG 3
#define STG_BYTES 32768        // A 16K | W 16K
#define NCHUNK 32              // per split: 2048 / 64
#define SMEM_SIZE (NSTG * STG_BYTES + 1024)

__device__ __forceinline__ void load_stage(uint32_t orig, int st, int c,
                                           int t, int m0, int n0, size_t kbase) {
    uint32_t sb = orig + st * STG_BYTES;
    size_t ko = kbase + (size_t)c * 64;
#pragma unroll
    for (int j = 0; j < 4; j++) {          // A: 128 rows x 8 chunks = 1024
        int idx = t + j * 256;
        int row = idx >> 3, ck = idx & 7;
        cp16(sb + SWADDR(row, ck), g_A + (size_t)(m0 + row) * Kz + ko + ck * 8);
    }
#pragma unroll
    for (int j = 0; j < 4; j++) {          // W: 128 rows x 8 chunks = 1024
        int idx = t + j * 256;
        int row = idx >> 3, ck = idx & 7;
        cp16(sb + 16384 + SWADDR(row, ck), g_W + (size_t)(n0 + row) * Kz + ko + ck * 8);
    }
}

__global__ __launch_bounds__(256, 2) void gemm_kernel(float* __restrict__ out) {
    extern __shared__ unsigned char smem_raw[];
    uint32_t orig = (smem_u32(smem_raw) + 1023u) & ~1023u;

    int t    = threadIdx.x;
    int lane = t & 31;
    int wid  = t >> 5;
    int wm   = wid >> 1;         // 0..3 -> 32-row band
    int wn   = wid & 1;          // 0..1 -> 64-col band
    int m0   = blockIdx.y * BM;
    int n0   = blockIdx.x * BN;
    int z    = blockIdx.z;
    size_t kbase = (size_t)z * 2048;

    float acc[2][8][4];
#pragma unroll
    for (int mt = 0; mt < 2; mt++)
#pragma unroll
        for (int nt = 0; nt < 8; nt++)
#pragma unroll
            for (int r = 0; r < 4; r++) acc[mt][nt][r] = 0.0f;

    // per-lane ldmatrix address components
    int a_row_base = wm * 32 + (lane & 15);                 // + mt*16
    int a_ckx      = lane >> 4;                             // k-half select
    int b_n_off    = ((lane >> 4) & 1) * 8 + (lane & 7);    // + wn*64 + q*16
    int b_ckx      = (lane >> 3) & 1;

    // prologue: 2 stages in flight
    load_stage(orig, 0, 0, t, m0, n0, kbase); cp_commit();
    load_stage(orig, 1, 1, t, m0, n0, kbase); cp_commit();

    for (int c = 0; c < NCHUNK; c++) {
        cp_wait1();
        __syncthreads();   // single barrier per chunk (orders stage reuse too)

        if (c + 2 < NCHUNK) load_stage(orig, (c + 2) % NSTG, c + 2, t, m0, n0, kbase);
        cp_commit();

        uint32_t sb = orig + (c % NSTG) * STG_BYTES;
#pragma unroll
        for (int ks = 0; ks < 4; ks++) {
            uint32_t av[2][4], bv[4][4];
#pragma unroll
            for (int mt = 0; mt < 2; mt++)
                ldsm4(av[mt], sb + SWADDR(a_row_base + mt * 16, ks * 2 + a_ckx));
#pragma unroll
            for (int q = 0; q < 4; q++) {
                int n = wn * 64 + q * 16 + b_n_off;
                ldsm4(bv[q], sb + 16384 + SWADDR(n, ks * 2 + b_ckx));
            }
#pragma unroll
            for (int mt = 0; mt < 2; mt++)
#pragma unroll
                for (int nt = 0; nt < 8; nt++) {
                    int q = nt >> 1, pr = (nt & 1) * 2;
                    mma16816(acc[mt][nt], av[mt], &bv[q][pr]);
                }
        }
    }

    // epilogue: red.global.add into out (pre-initialized with bias)
#pragma unroll
    for (int mt = 0; mt < 2; mt++) {
        int row = m0 + wm * 32 + mt * 16 + (lane >> 2);
#pragma unroll
        for (int nt = 0; nt < 8; nt++) {
            int col = n0 + wn * 64 + nt * 8 + (lane & 3) * 2;
            float* p0 = out + (size_t)row * Oz + col;
            float* p1 = out + (size_t)(row + 8) * Oz + col;
            redadd(p0,     acc[mt][nt][0]);
            redadd(p0 + 1, acc[mt][nt][1]);
            redadd(p1,     acc[mt][nt][2]);
            redadd(p1 + 1, acc[mt][nt][3]);
        }
    }
}

// -------------------------------------------------------------- launcher --
extern "C" void kernel_launch(void* const* d_in, const int* in_sizes, int n_in,
                              void* d_out, int out_size) {
    const float* x    = (const float*)d_in[0];
    const float* coef = (const float*)d_in[1];
    const float* bias = (const float*)d_in[2];
    float* out = (float*)d_out;

    static int configured = 0;
    if (!configured) {
        cudaFuncSetAttribute(gemm_kernel,
                             cudaFuncAttributeMaxDynamicSharedMemorySize, SMEM_SIZE);
        configured = 1;
    }

    prep_kernel<<<7168, 256>>>(x, coef, bias, out);
    dim3 grid(Oz / BN, Bz / BM, 4);   // (2, 32, 4) = 256 CTAs
    gemm_kernel<<<grid, 256, SMEM_SIZE>>>(out);
}